// round 5
// baseline (speedup 1.0000x reference)
#include <cuda_runtime.h>
#include <stdint.h>

#define NN 50000
#define NE 800000
#define DD 64

// scratch (no allocations allowed). Zero-initialized at module load.
// INVARIANT: g_cnt == 0 at entry of every kernel_launch call (fill_kernel
// decrements it back to zero each call).
__device__ float g_agg[NN * DD];     // holds h_in = x + sum(neighbors)
__device__ float g_y0[NN * DD];      // layer-0 output
__device__ int   g_cnt[NN];
__device__ int   g_rowptr[NN + 1];
__device__ int   g_col[NE];

// ---------------------------------------------------------------------------
// CSR build: hist -> scan (single block) -> fill
// ---------------------------------------------------------------------------
__global__ void hist_kernel(const int* __restrict__ dst) {
    int e = blockIdx.x * blockDim.x + threadIdx.x;
    if (e < NE) atomicAdd(&g_cnt[dst[e]], 1);
}

#define SCAN_T 1024
#define SCAN_ITEMS ((NN + SCAN_T - 1) / SCAN_T)   // 49

__global__ void __launch_bounds__(SCAN_T)
scan_kernel() {
    __shared__ int part[SCAN_T];
    int t = threadIdx.x;
    int base = t * SCAN_ITEMS;

    int sum = 0;
    #pragma unroll 7
    for (int i = 0; i < SCAN_ITEMS; i++) {
        int idx = base + i;
        if (idx < NN) sum += g_cnt[idx];
    }
    part[t] = sum;
    __syncthreads();

    #pragma unroll
    for (int off = 1; off < SCAN_T; off <<= 1) {
        int add = (t >= off) ? part[t - off] : 0;
        __syncthreads();
        part[t] += add;
        __syncthreads();
    }

    int run = (t > 0) ? part[t - 1] : 0;   // exclusive prefix of this chunk
    if (t == 0) g_rowptr[0] = 0;
    #pragma unroll 7
    for (int i = 0; i < SCAN_ITEMS; i++) {
        int idx = base + i;
        if (idx < NN) {
            run += g_cnt[idx];
            g_rowptr[idx + 1] = run;
        }
    }
}

// decrementing fill: restores g_cnt to 0 for the next call
__global__ void fill_kernel(const int* __restrict__ src,
                            const int* __restrict__ dst) {
    int e = blockIdx.x * blockDim.x + threadIdx.x;
    if (e < NE) {
        int d = dst[e];
        int pos = atomicSub(&g_cnt[d], 1) - 1;   // deg-1 .. 0
        g_col[g_rowptr[d] + pos] = src[e];
    }
}

// ---------------------------------------------------------------------------
// aggregation gather: g_agg[n] = X[n] + sum_{j in N_in(n)} X[j]
// half-warp (16 lanes) per node, one float4 per lane, 4-wide unroll.
// ---------------------------------------------------------------------------
__global__ void __launch_bounds__(256)
gather_kernel(const float* __restrict__ xin, int in_scratch) {
    const float* __restrict__ base = in_scratch ? g_y0 : xin;
    int t = blockIdx.x * blockDim.x + threadIdx.x;
    int node = t >> 4;
    if (node >= NN) return;
    int col = (t & 15) << 2;

    float4 acc = *(const float4*)(base + (size_t)node * DD + col);

    int p   = g_rowptr[node];
    int end = g_rowptr[node + 1];

    for (; p + 3 < end; p += 4) {
        int j0 = g_col[p];
        int j1 = g_col[p + 1];
        int j2 = g_col[p + 2];
        int j3 = g_col[p + 3];
        float4 a = *(const float4*)(base + (size_t)j0 * DD + col);
        float4 b = *(const float4*)(base + (size_t)j1 * DD + col);
        float4 c = *(const float4*)(base + (size_t)j2 * DD + col);
        float4 d = *(const float4*)(base + (size_t)j3 * DD + col);
        acc.x += (a.x + b.x) + (c.x + d.x);
        acc.y += (a.y + b.y) + (c.y + d.y);
        acc.z += (a.z + b.z) + (c.z + d.z);
        acc.w += (a.w + b.w) + (c.w + d.w);
    }
    for (; p < end; p++) {
        int j0 = g_col[p];
        float4 a = *(const float4*)(base + (size_t)j0 * DD + col);
        acc.x += a.x; acc.y += a.y; acc.z += a.z; acc.w += a.w;
    }

    *(float4*)(g_agg + (size_t)node * DD + col) = acc;
}

// ---------------------------------------------------------------------------
// fused MLP, packed f32x2 FMA: out = tanh(g_agg @ W1 + b1) @ W2 + b2
// block = 128 threads, 64-node tile. thread (ng,cg) owns rows {ng+16j},
// cols [8cg, 8cg+8) as 4 f32x2 pairs.
// ---------------------------------------------------------------------------
__device__ __forceinline__ float fast_tanh(float x) {
    float y;
    asm("tanh.approx.f32 %0, %1;" : "=f"(y) : "f"(x));
    return y;
}

__device__ __forceinline__ void ffma2(unsigned long long& d,
                                      unsigned long long a,
                                      unsigned long long b) {
    asm("fma.rn.f32x2 %0, %1, %2, %0;" : "+l"(d) : "l"(a), "l"(b));
}

__device__ __forceinline__ unsigned long long pack2(float v) {
    unsigned long long r;
    asm("mov.b64 %0, {%1, %1};" : "=l"(r) : "f"(v));
    return r;
}

__device__ __forceinline__ float lo32(unsigned long long v) {
    return __uint_as_float((unsigned)(v & 0xffffffffull));
}
__device__ __forceinline__ float hi32(unsigned long long v) {
    return __uint_as_float((unsigned)(v >> 32));
}

#define T_STRIDE 65

__global__ void __launch_bounds__(128, 2)
mlp_kernel(const float* __restrict__ w1, const float* __restrict__ b1,
           const float* __restrict__ w2, const float* __restrict__ b2,
           float* __restrict__ out, int out_scratch) {
    extern __shared__ float sm[];
    float* sW1 = sm;                    // 64*64
    float* sW2 = sm + 4096;             // 64*64
    float* sT  = sm + 8192;             // 64 * T_STRIDE
    float* sH  = sT + 64 * T_STRIDE;    // 64 * T_STRIDE

    float* __restrict__ o = out_scratch ? g_y0 : out;

    const int tid = threadIdx.x;
    const int n0 = blockIdx.x * 64;

    // ---- load weights into smem ----
    #pragma unroll
    for (int rep = 0; rep < 8; rep++) {
        int f4 = rep * 128 + tid;
        ((float4*)sW1)[f4] = ((const float4*)w1)[f4];
        ((float4*)sW2)[f4] = ((const float4*)w2)[f4];
    }

    // ---- load node tile into sT ----
    #pragma unroll
    for (int rep = 0; rep < 8; rep++) {
        int f4 = rep * 128 + tid;
        int n = f4 >> 4;
        int k = (f4 & 15) << 2;
        float4 v;
        if (n0 + n < NN) {
            v = *(const float4*)(g_agg + (size_t)(n0 + n) * DD + k);
        } else {
            v = make_float4(0.f, 0.f, 0.f, 0.f);
        }
        float* p = sT + n * T_STRIDE + k;
        p[0] = v.x; p[1] = v.y; p[2] = v.z; p[3] = v.w;
    }
    __syncthreads();

    const int ng = tid & 15;   // row within each 16-row group
    const int cg = tid >> 4;   // col group (8 cols)
    const int cb = cg * 8;

    unsigned long long acc[4][4];   // [row j][pair u] — 8 fp32 cols as 4 pairs

    // ---- GEMM1: h = T @ W1 + b1 ----
    {
        ulonglong2 bp0 = *(const ulonglong2*)(b1 + cb);
        ulonglong2 bp1 = *(const ulonglong2*)(b1 + cb + 4);
        #pragma unroll
        for (int j = 0; j < 4; j++) {
            acc[j][0] = bp0.x; acc[j][1] = bp0.y;
            acc[j][2] = bp1.x; acc[j][3] = bp1.y;
        }
        #pragma unroll 4
        for (int k = 0; k < 64; k++) {
            ulonglong2 wp0 = *(const ulonglong2*)(sW1 + k * 64 + cb);
            ulonglong2 wp1 = *(const ulonglong2*)(sW1 + k * 64 + cb + 4);
            #pragma unroll
            for (int j = 0; j < 4; j++) {
                unsigned long long tp = pack2(sT[(ng + 16 * j) * T_STRIDE + k]);
                ffma2(acc[j][0], wp0.x, tp);
                ffma2(acc[j][1], wp0.y, tp);
                ffma2(acc[j][2], wp1.x, tp);
                ffma2(acc[j][3], wp1.y, tp);
            }
        }
    }

    // ---- tanh + stage h ----
    #pragma unroll
    for (int j = 0; j < 4; j++) {
        float* hrow = sH + (ng + 16 * j) * T_STRIDE + cb;
        #pragma unroll
        for (int u = 0; u < 4; u++) {
            hrow[2 * u]     = fast_tanh(lo32(acc[j][u]));
            hrow[2 * u + 1] = fast_tanh(hi32(acc[j][u]));
        }
    }
    __syncthreads();

    // ---- GEMM2: y = H @ W2 + b2 ----
    {
        ulonglong2 bp0 = *(const ulonglong2*)(b2 + cb);
        ulonglong2 bp1 = *(const ulonglong2*)(b2 + cb + 4);
        #pragma unroll
        for (int j = 0; j < 4; j++) {
            acc[j][0] = bp0.x; acc[j][1] = bp0.y;
            acc[j][2] = bp1.x; acc[j][3] = bp1.y;
        }
        #pragma unroll 4
        for (int k = 0; k < 64; k++) {
            ulonglong2 wp0 = *(const ulonglong2*)(sW2 + k * 64 + cb);
            ulonglong2 wp1 = *(const ulonglong2*)(sW2 + k * 64 + cb + 4);
            #pragma unroll
            for (int j = 0; j < 4; j++) {
                unsigned long long tp = pack2(sH[(ng + 16 * j) * T_STRIDE + k]);
                ffma2(acc[j][0], wp0.x, tp);
                ffma2(acc[j][1], wp0.y, tp);
                ffma2(acc[j][2], wp1.x, tp);
                ffma2(acc[j][3], wp1.y, tp);
            }
        }
    }

    // ---- store (pairs are bit-exact fp32 couples) ----
    #pragma unroll
    for (int j = 0; j < 4; j++) {
        int n = n0 + ng + 16 * j;
        if (n < NN) {
            *(ulonglong2*)(o + (size_t)n * DD + cb) =
                make_ulonglong2(acc[j][0], acc[j][1]);
            *(ulonglong2*)(o + (size_t)n * DD + cb + 4) =
                make_ulonglong2(acc[j][2], acc[j][3]);
        }
    }
}

// ---------------------------------------------------------------------------
// launch
// ---------------------------------------------------------------------------
extern "C" void kernel_launch(void* const* d_in, const int* in_sizes, int n_in,
                              void* d_out, int out_size) {
    const float* x    = (const float*)d_in[0];
    const int*   src  = (const int*)d_in[1];
    const int*   dst  = (const int*)d_in[2];
    const float* w1_0 = (const float*)d_in[3];
    const float* b1_0 = (const float*)d_in[4];
    const float* w2_0 = (const float*)d_in[5];
    const float* b2_0 = (const float*)d_in[6];
    const float* w1_1 = (const float*)d_in[7];
    const float* b1_1 = (const float*)d_in[8];
    const float* w2_1 = (const float*)d_in[9];
    const float* b2_1 = (const float*)d_in[10];
    float* out = (float*)d_out;

    const int smem_bytes = (4096 * 2 + 64 * T_STRIDE * 2) * sizeof(float);
    cudaFuncSetAttribute(mlp_kernel, cudaFuncAttributeMaxDynamicSharedMemorySize,
                         smem_bytes);

    const int edgeb = (NE + 255) / 256;
    const int gathb = (NN * 16 + 255) / 256;
    const int mlpb  = (NN + 63) / 64;

    // ---- CSR build (g_cnt is 0 on entry; fill restores it to 0) ----
    hist_kernel<<<edgeb, 256>>>(dst);
    scan_kernel<<<1, SCAN_T>>>();
    fill_kernel<<<edgeb, 256>>>(src, dst);

    // ---- layer 0 ----
    gather_kernel<<<gathb, 256>>>(x, /*in_scratch=*/0);
    mlp_kernel<<<mlpb, 128, smem_bytes>>>(w1_0, b1_0, w2_0, b2_0,
                                          out, /*out_scratch=*/1);

    // ---- layer 1 ----
    gather_kernel<<<gathb, 256>>>(nullptr, /*in_scratch=*/1);
    mlp_kernel<<<mlpb, 128, smem_bytes>>>(w1_1, b1_1, w2_1, b2_1,
                                          out, /*out_scratch=*/0);
}

// round 6
// speedup vs baseline: 1.0435x; 1.0435x over previous
#include <cuda_runtime.h>
#include <stdint.h>

#define NN 50000
#define NE 800000
#define DD 64

// scratch (no allocations allowed). Zero-initialized at module load.
// INVARIANT: g_cnt == 0 at entry of every kernel_launch call (fill_kernel
// decrements it back to zero each call).
__device__ float g_agg[NN * DD];     // holds h_in = x + sum(neighbors)
__device__ float g_y0[NN * DD];      // layer-0 output
__device__ int   g_cnt[NN];
__device__ int   g_rowptr[NN + 1];
__device__ int   g_col[NE];

// ---------------------------------------------------------------------------
// CSR build: hist -> scan (single block) -> fill
// ---------------------------------------------------------------------------
__global__ void hist_kernel(const int* __restrict__ dst) {
    int e = blockIdx.x * blockDim.x + threadIdx.x;
    if (e < NE) atomicAdd(&g_cnt[dst[e]], 1);
}

#define SCAN_T 1024
#define SCAN_ITEMS ((NN + SCAN_T - 1) / SCAN_T)   // 49

__global__ void __launch_bounds__(SCAN_T)
scan_kernel() {
    __shared__ int part[SCAN_T];
    int t = threadIdx.x;
    int base = t * SCAN_ITEMS;

    int sum = 0;
    #pragma unroll 7
    for (int i = 0; i < SCAN_ITEMS; i++) {
        int idx = base + i;
        if (idx < NN) sum += g_cnt[idx];
    }
    part[t] = sum;
    __syncthreads();

    #pragma unroll
    for (int off = 1; off < SCAN_T; off <<= 1) {
        int add = (t >= off) ? part[t - off] : 0;
        __syncthreads();
        part[t] += add;
        __syncthreads();
    }

    int run = (t > 0) ? part[t - 1] : 0;   // exclusive prefix of this chunk
    if (t == 0) g_rowptr[0] = 0;
    #pragma unroll 7
    for (int i = 0; i < SCAN_ITEMS; i++) {
        int idx = base + i;
        if (idx < NN) {
            run += g_cnt[idx];
            g_rowptr[idx + 1] = run;
        }
    }
}

// decrementing fill: restores g_cnt to 0 for the next call
__global__ void fill_kernel(const int* __restrict__ src,
                            const int* __restrict__ dst) {
    int e = blockIdx.x * blockDim.x + threadIdx.x;
    if (e < NE) {
        int d = dst[e];
        int pos = atomicSub(&g_cnt[d], 1) - 1;   // deg-1 .. 0
        g_col[g_rowptr[d] + pos] = src[e];
    }
}

// ---------------------------------------------------------------------------
// aggregation gather: g_agg[n] = X[n] + sum_{j in N_in(n)} X[j]
// half-warp (16 lanes) per node, one float4 per lane, 4-wide unroll.
// (measured at the LTS roofline — do not touch)
// ---------------------------------------------------------------------------
__global__ void __launch_bounds__(256)
gather_kernel(const float* __restrict__ xin, int in_scratch) {
    const float* __restrict__ base = in_scratch ? g_y0 : xin;
    int t = blockIdx.x * blockDim.x + threadIdx.x;
    int node = t >> 4;
    if (node >= NN) return;
    int col = (t & 15) << 2;

    float4 acc = *(const float4*)(base + (size_t)node * DD + col);

    int p   = g_rowptr[node];
    int end = g_rowptr[node + 1];

    for (; p + 3 < end; p += 4) {
        int j0 = g_col[p];
        int j1 = g_col[p + 1];
        int j2 = g_col[p + 2];
        int j3 = g_col[p + 3];
        float4 a = *(const float4*)(base + (size_t)j0 * DD + col);
        float4 b = *(const float4*)(base + (size_t)j1 * DD + col);
        float4 c = *(const float4*)(base + (size_t)j2 * DD + col);
        float4 d = *(const float4*)(base + (size_t)j3 * DD + col);
        acc.x += (a.x + b.x) + (c.x + d.x);
        acc.y += (a.y + b.y) + (c.y + d.y);
        acc.z += (a.z + b.z) + (c.z + d.z);
        acc.w += (a.w + b.w) + (c.w + d.w);
    }
    for (; p < end; p++) {
        int j0 = g_col[p];
        float4 a = *(const float4*)(base + (size_t)j0 * DD + col);
        acc.x += a.x; acc.y += a.y; acc.z += a.z; acc.w += a.w;
    }

    *(float4*)(g_agg + (size_t)node * DD + col) = acc;
}

// ---------------------------------------------------------------------------
// fused MLP (scalar FFMA): out = tanh(g_agg @ W1 + b1) @ W2 + b2
// block = 128 threads, 64-node tile. thread (ng,cg) owns rows {ng+16j},
// cols [8cg, 8cg+8). sH aliases sT (tile fully consumed before tanh write).
// ---------------------------------------------------------------------------
__device__ __forceinline__ float fast_tanh(float x) {
    float y;
    asm("tanh.approx.f32 %0, %1;" : "=f"(y) : "f"(x));
    return y;
}

#define T_STRIDE 65
#define SMEM_FLOATS (4096 * 2 + 64 * T_STRIDE)   // 12352 floats = 49408 B

__global__ void __launch_bounds__(128, 4)
mlp_kernel(const float* __restrict__ w1, const float* __restrict__ b1,
           const float* __restrict__ w2, const float* __restrict__ b2,
           float* __restrict__ out, int out_scratch) {
    extern __shared__ float sm[];
    float* sW1 = sm;                    // 64*64
    float* sW2 = sm + 4096;             // 64*64
    float* sT  = sm + 8192;             // 64 * T_STRIDE (reused for tanh(h))

    float* __restrict__ o = out_scratch ? g_y0 : out;

    const int tid = threadIdx.x;
    const int n0 = blockIdx.x * 64;

    // ---- load weights into smem ----
    #pragma unroll
    for (int rep = 0; rep < 8; rep++) {
        int f4 = rep * 128 + tid;
        ((float4*)sW1)[f4] = ((const float4*)w1)[f4];
        ((float4*)sW2)[f4] = ((const float4*)w2)[f4];
    }

    // ---- load node tile into sT ----
    #pragma unroll
    for (int rep = 0; rep < 8; rep++) {
        int f4 = rep * 128 + tid;
        int n = f4 >> 4;
        int k = (f4 & 15) << 2;
        float4 v;
        if (n0 + n < NN) {
            v = *(const float4*)(g_agg + (size_t)(n0 + n) * DD + k);
        } else {
            v = make_float4(0.f, 0.f, 0.f, 0.f);
        }
        float* p = sT + n * T_STRIDE + k;
        p[0] = v.x; p[1] = v.y; p[2] = v.z; p[3] = v.w;
    }
    __syncthreads();

    const int ng = tid & 15;   // row within each 16-row group (bank-clean)
    const int cg = tid >> 4;   // col group (8 cols)
    const int cb = cg * 8;

    float acc[4][8];

    // ---- GEMM1: h = T @ W1 + b1 ----
    {
        float bv[8];
        #pragma unroll
        for (int u = 0; u < 8; u++) bv[u] = b1[cb + u];
        #pragma unroll
        for (int j = 0; j < 4; j++)
            #pragma unroll
            for (int u = 0; u < 8; u++) acc[j][u] = bv[u];

        #pragma unroll 4
        for (int k = 0; k < 64; k++) {
            float4 wA = *(const float4*)(sW1 + k * 64 + cb);
            float4 wB = *(const float4*)(sW1 + k * 64 + cb + 4);
            float w[8] = {wA.x, wA.y, wA.z, wA.w, wB.x, wB.y, wB.z, wB.w};
            #pragma unroll
            for (int j = 0; j < 4; j++) {
                float tv = sT[(ng + 16 * j) * T_STRIDE + k];
                #pragma unroll
                for (int u = 0; u < 8; u++) acc[j][u] += tv * w[u];
            }
        }
    }

    // ---- tanh; overwrite sT (everyone has finished reading it) ----
    __syncthreads();
    #pragma unroll
    for (int j = 0; j < 4; j++) {
        float* hrow = sT + (ng + 16 * j) * T_STRIDE + cb;
        #pragma unroll
        for (int u = 0; u < 8; u++)
            hrow[u] = fast_tanh(acc[j][u]);
    }
    __syncthreads();

    // ---- GEMM2: y = H @ W2 + b2 ----
    {
        float bv[8];
        #pragma unroll
        for (int u = 0; u < 8; u++) bv[u] = b2[cb + u];
        #pragma unroll
        for (int j = 0; j < 4; j++)
            #pragma unroll
            for (int u = 0; u < 8; u++) acc[j][u] = bv[u];

        #pragma unroll 4
        for (int k = 0; k < 64; k++) {
            float4 wA = *(const float4*)(sW2 + k * 64 + cb);
            float4 wB = *(const float4*)(sW2 + k * 64 + cb + 4);
            float w[8] = {wA.x, wA.y, wA.z, wA.w, wB.x, wB.y, wB.z, wB.w};
            #pragma unroll
            for (int j = 0; j < 4; j++) {
                float hv = sT[(ng + 16 * j) * T_STRIDE + k];
                #pragma unroll
                for (int u = 0; u < 8; u++) acc[j][u] += hv * w[u];
            }
        }
    }

    // ---- store ----
    #pragma unroll
    for (int j = 0; j < 4; j++) {
        int n = n0 + ng + 16 * j;
        if (n < NN) {
            float4 o1 = make_float4(acc[j][0], acc[j][1], acc[j][2], acc[j][3]);
            float4 o2 = make_float4(acc[j][4], acc[j][5], acc[j][6], acc[j][7]);
            *(float4*)(o + (size_t)n * DD + cb) = o1;
            *(float4*)(o + (size_t)n * DD + cb + 4) = o2;
        }
    }
}

// ---------------------------------------------------------------------------
// launch
// ---------------------------------------------------------------------------
extern "C" void kernel_launch(void* const* d_in, const int* in_sizes, int n_in,
                              void* d_out, int out_size) {
    const float* x    = (const float*)d_in[0];
    const int*   src  = (const int*)d_in[1];
    const int*   dst  = (const int*)d_in[2];
    const float* w1_0 = (const float*)d_in[3];
    const float* b1_0 = (const float*)d_in[4];
    const float* w2_0 = (const float*)d_in[5];
    const float* b2_0 = (const float*)d_in[6];
    const float* w1_1 = (const float*)d_in[7];
    const float* b1_1 = (const float*)d_in[8];
    const float* w2_1 = (const float*)d_in[9];
    const float* b2_1 = (const float*)d_in[10];
    float* out = (float*)d_out;

    const int smem_bytes = SMEM_FLOATS * sizeof(float);   // 49408 B
    cudaFuncSetAttribute(mlp_kernel, cudaFuncAttributeMaxDynamicSharedMemorySize,
                         smem_bytes);

    const int edgeb = (NE + 255) / 256;
    const int gathb = (NN * 16 + 255) / 256;
    const int mlpb  = (NN + 63) / 64;

    // ---- CSR build (g_cnt is 0 on entry; fill restores it to 0) ----
    hist_kernel<<<edgeb, 256>>>(dst);
    scan_kernel<<<1, SCAN_T>>>();
    fill_kernel<<<edgeb, 256>>>(src, dst);

    // ---- layer 0 ----
    gather_kernel<<<gathb, 256>>>(x, /*in_scratch=*/0);
    mlp_kernel<<<mlpb, 128, smem_bytes>>>(w1_0, b1_0, w2_0, b2_0,
                                          out, /*out_scratch=*/1);

    // ---- layer 1 ----
    gather_kernel<<<gathb, 256>>>(nullptr, /*in_scratch=*/1);
    mlp_kernel<<<mlpb, 128, smem_bytes>>>(w1_1, b1_1, w2_1, b2_1,
                                          out, /*out_scratch=*/0);
}

// round 7
// speedup vs baseline: 1.4218x; 1.3625x over previous
#include <cuda_runtime.h>
#include <stdint.h>

#define NN 50000
#define NE 800000
#define DD 64

#define SCAN_T 1024
#define NCHUNK ((NN + SCAN_T - 1) / SCAN_T)   // 49

// scratch (no allocations allowed). Zero-initialized at module load.
// INVARIANT: g_cnt == 0 at entry of every kernel_launch call (fill_kernel
// decrements it back to zero each call).
__device__ float g_agg[NN * DD];     // holds h_in = x + sum(neighbors)
__device__ float g_y0[NN * DD];      // layer-0 output
__device__ int   g_cnt[NN];
__device__ int   g_rowptr[NN + 1];
__device__ int   g_col[NE];
__device__ int   g_part[NCHUNK];

// ---------------------------------------------------------------------------
// CSR build: hist -> scan1 (per-chunk, coalesced) -> scan2_add -> fill
// ---------------------------------------------------------------------------
__global__ void hist_kernel(const int* __restrict__ dst) {
    int e = blockIdx.x * blockDim.x + threadIdx.x;
    if (e < NE) atomicAdd(&g_cnt[dst[e]], 1);
}

// per-chunk inclusive scan (coalesced), chunk totals -> g_part
__global__ void __launch_bounds__(SCAN_T)
scan1_kernel() {
    __shared__ int s[SCAN_T];
    int t = threadIdx.x;
    int i = blockIdx.x * SCAN_T + t;
    int v = (i < NN) ? g_cnt[i] : 0;
    s[t] = v;
    __syncthreads();
    #pragma unroll
    for (int off = 1; off < SCAN_T; off <<= 1) {
        int add = (t >= off) ? s[t - off] : 0;
        __syncthreads();
        s[t] += add;
        __syncthreads();
    }
    if (i < NN) g_rowptr[i + 1] = s[t];
    if (t == SCAN_T - 1) g_part[blockIdx.x] = s[t];
    if (i == 0) g_rowptr[0] = 0;
}

// add prefix of chunk totals; each block redundantly reduces <=48 ints (L2-hot)
__global__ void __launch_bounds__(SCAN_T)
scan2_add_kernel() {
    __shared__ int s_off;
    int b = blockIdx.x;
    if (b == 0) return;
    int t = threadIdx.x;
    if (t < 32) {
        int acc = 0;
        for (int j = t; j < b; j += 32) acc += g_part[j];
        #pragma unroll
        for (int o = 16; o > 0; o >>= 1)
            acc += __shfl_down_sync(0xffffffffu, acc, o);
        if (t == 0) s_off = acc;
    }
    __syncthreads();
    int off = s_off;
    int i = b * SCAN_T + t;
    if (i < NN) g_rowptr[i + 1] += off;
}

// decrementing fill: restores g_cnt to 0 for the next call
__global__ void fill_kernel(const int* __restrict__ src,
                            const int* __restrict__ dst) {
    int e = blockIdx.x * blockDim.x + threadIdx.x;
    if (e < NE) {
        int d = dst[e];
        int pos = atomicSub(&g_cnt[d], 1) - 1;   // deg-1 .. 0
        g_col[g_rowptr[d] + pos] = src[e];
    }
}

// ---------------------------------------------------------------------------
// aggregation gather: g_agg[n] = X[n] + sum_{j in N_in(n)} X[j]
// half-warp (16 lanes) per node, one float4 per lane, 4-wide unroll.
// (measured at the LTS roofline — do not touch)
// ---------------------------------------------------------------------------
__global__ void __launch_bounds__(256)
gather_kernel(const float* __restrict__ xin, int in_scratch) {
    const float* __restrict__ base = in_scratch ? g_y0 : xin;
    int t = blockIdx.x * blockDim.x + threadIdx.x;
    int node = t >> 4;
    if (node >= NN) return;
    int col = (t & 15) << 2;

    float4 acc = *(const float4*)(base + (size_t)node * DD + col);

    int p   = g_rowptr[node];
    int end = g_rowptr[node + 1];

    for (; p + 3 < end; p += 4) {
        int j0 = g_col[p];
        int j1 = g_col[p + 1];
        int j2 = g_col[p + 2];
        int j3 = g_col[p + 3];
        float4 a = *(const float4*)(base + (size_t)j0 * DD + col);
        float4 b = *(const float4*)(base + (size_t)j1 * DD + col);
        float4 c = *(const float4*)(base + (size_t)j2 * DD + col);
        float4 d = *(const float4*)(base + (size_t)j3 * DD + col);
        acc.x += (a.x + b.x) + (c.x + d.x);
        acc.y += (a.y + b.y) + (c.y + d.y);
        acc.z += (a.z + b.z) + (c.z + d.z);
        acc.w += (a.w + b.w) + (c.w + d.w);
    }
    for (; p < end; p++) {
        int j0 = g_col[p];
        float4 a = *(const float4*)(base + (size_t)j0 * DD + col);
        acc.x += a.x; acc.y += a.y; acc.z += a.z; acc.w += a.w;
    }

    *(float4*)(g_agg + (size_t)node * DD + col) = acc;
}

// ---------------------------------------------------------------------------
// fused MLP (scalar FFMA): out = tanh(g_agg @ W1 + b1) @ W2 + b2
// block = 128 threads, 64-node tile. thread (ng,cg) owns rows {ng+16j},
// cols [8cg, 8cg+8). sH aliases sT (tile fully consumed before tanh write).
// ---------------------------------------------------------------------------
__device__ __forceinline__ float fast_tanh(float x) {
    float y;
    asm("tanh.approx.f32 %0, %1;" : "=f"(y) : "f"(x));
    return y;
}

#define T_STRIDE 65
#define SMEM_FLOATS (4096 * 2 + 64 * T_STRIDE)   // 12352 floats = 49408 B

__global__ void __launch_bounds__(128, 4)
mlp_kernel(const float* __restrict__ w1, const float* __restrict__ b1,
           const float* __restrict__ w2, const float* __restrict__ b2,
           float* __restrict__ out, int out_scratch) {
    extern __shared__ float sm[];
    float* sW1 = sm;                    // 64*64
    float* sW2 = sm + 4096;             // 64*64
    float* sT  = sm + 8192;             // 64 * T_STRIDE (reused for tanh(h))

    float* __restrict__ o = out_scratch ? g_y0 : out;

    const int tid = threadIdx.x;
    const int n0 = blockIdx.x * 64;

    // ---- load weights into smem ----
    #pragma unroll
    for (int rep = 0; rep < 8; rep++) {
        int f4 = rep * 128 + tid;
        ((float4*)sW1)[f4] = ((const float4*)w1)[f4];
        ((float4*)sW2)[f4] = ((const float4*)w2)[f4];
    }

    // ---- load node tile into sT ----
    #pragma unroll
    for (int rep = 0; rep < 8; rep++) {
        int f4 = rep * 128 + tid;
        int n = f4 >> 4;
        int k = (f4 & 15) << 2;
        float4 v;
        if (n0 + n < NN) {
            v = *(const float4*)(g_agg + (size_t)(n0 + n) * DD + k);
        } else {
            v = make_float4(0.f, 0.f, 0.f, 0.f);
        }
        float* p = sT + n * T_STRIDE + k;
        p[0] = v.x; p[1] = v.y; p[2] = v.z; p[3] = v.w;
    }
    __syncthreads();

    const int ng = tid & 15;   // row within each 16-row group (bank-clean)
    const int cg = tid >> 4;   // col group (8 cols)
    const int cb = cg * 8;

    float acc[4][8];

    // ---- GEMM1: h = T @ W1 + b1 ----
    {
        float bv[8];
        #pragma unroll
        for (int u = 0; u < 8; u++) bv[u] = b1[cb + u];
        #pragma unroll
        for (int j = 0; j < 4; j++)
            #pragma unroll
            for (int u = 0; u < 8; u++) acc[j][u] = bv[u];

        #pragma unroll 4
        for (int k = 0; k < 64; k++) {
            float4 wA = *(const float4*)(sW1 + k * 64 + cb);
            float4 wB = *(const float4*)(sW1 + k * 64 + cb + 4);
            float w[8] = {wA.x, wA.y, wA.z, wA.w, wB.x, wB.y, wB.z, wB.w};
            #pragma unroll
            for (int j = 0; j < 4; j++) {
                float tv = sT[(ng + 16 * j) * T_STRIDE + k];
                #pragma unroll
                for (int u = 0; u < 8; u++) acc[j][u] += tv * w[u];
            }
        }
    }

    // ---- tanh; overwrite sT (everyone has finished reading it) ----
    __syncthreads();
    #pragma unroll
    for (int j = 0; j < 4; j++) {
        float* hrow = sT + (ng + 16 * j) * T_STRIDE + cb;
        #pragma unroll
        for (int u = 0; u < 8; u++)
            hrow[u] = fast_tanh(acc[j][u]);
    }
    __syncthreads();

    // ---- GEMM2: y = H @ W2 + b2 ----
    {
        float bv[8];
        #pragma unroll
        for (int u = 0; u < 8; u++) bv[u] = b2[cb + u];
        #pragma unroll
        for (int j = 0; j < 4; j++)
            #pragma unroll
            for (int u = 0; u < 8; u++) acc[j][u] = bv[u];

        #pragma unroll 4
        for (int k = 0; k < 64; k++) {
            float4 wA = *(const float4*)(sW2 + k * 64 + cb);
            float4 wB = *(const float4*)(sW2 + k * 64 + cb + 4);
            float w[8] = {wA.x, wA.y, wA.z, wA.w, wB.x, wB.y, wB.z, wB.w};
            #pragma unroll
            for (int j = 0; j < 4; j++) {
                float hv = sT[(ng + 16 * j) * T_STRIDE + k];
                #pragma unroll
                for (int u = 0; u < 8; u++) acc[j][u] += hv * w[u];
            }
        }
    }

    // ---- store ----
    #pragma unroll
    for (int j = 0; j < 4; j++) {
        int n = n0 + ng + 16 * j;
        if (n < NN) {
            float4 o1 = make_float4(acc[j][0], acc[j][1], acc[j][2], acc[j][3]);
            float4 o2 = make_float4(acc[j][4], acc[j][5], acc[j][6], acc[j][7]);
            *(float4*)(o + (size_t)n * DD + cb) = o1;
            *(float4*)(o + (size_t)n * DD + cb + 4) = o2;
        }
    }
}

// ---------------------------------------------------------------------------
// launch
// ---------------------------------------------------------------------------
extern "C" void kernel_launch(void* const* d_in, const int* in_sizes, int n_in,
                              void* d_out, int out_size) {
    const float* x    = (const float*)d_in[0];
    const int*   src  = (const int*)d_in[1];
    const int*   dst  = (const int*)d_in[2];
    const float* w1_0 = (const float*)d_in[3];
    const float* b1_0 = (const float*)d_in[4];
    const float* w2_0 = (const float*)d_in[5];
    const float* b2_0 = (const float*)d_in[6];
    const float* w1_1 = (const float*)d_in[7];
    const float* b1_1 = (const float*)d_in[8];
    const float* w2_1 = (const float*)d_in[9];
    const float* b2_1 = (const float*)d_in[10];
    float* out = (float*)d_out;

    const int smem_bytes = SMEM_FLOATS * sizeof(float);   // 49408 B
    cudaFuncSetAttribute(mlp_kernel, cudaFuncAttributeMaxDynamicSharedMemorySize,
                         smem_bytes);

    const int edgeb = (NE + 255) / 256;
    const int gathb = (NN * 16 + 255) / 256;
    const int mlpb  = (NN + 63) / 64;

    // ---- CSR build (g_cnt is 0 on entry; fill restores it to 0) ----
    hist_kernel<<<edgeb, 256>>>(dst);
    scan1_kernel<<<NCHUNK, SCAN_T>>>();
    scan2_add_kernel<<<NCHUNK, SCAN_T>>>();
    fill_kernel<<<edgeb, 256>>>(src, dst);

    // ---- layer 0 ----
    gather_kernel<<<gathb, 256>>>(x, /*in_scratch=*/0);
    mlp_kernel<<<mlpb, 128, smem_bytes>>>(w1_0, b1_0, w2_0, b2_0,
                                          out, /*out_scratch=*/1);

    // ---- layer 1 ----
    gather_kernel<<<gathb, 256>>>(nullptr, /*in_scratch=*/1);
    mlp_kernel<<<mlpb, 128, smem_bytes>>>(w1_1, b1_1, w2_1, b2_1,
                                          out, /*out_scratch=*/0);
}

// round 8
// speedup vs baseline: 1.4443x; 1.0159x over previous
#include <cuda_runtime.h>
#include <cuda_fp16.h>
#include <stdint.h>

#define NN 50000
#define NE 800000
#define DD 64

#define SCAN_T 1024
#define NCHUNK ((NN + SCAN_T - 1) / SCAN_T)   // 49

// scratch (no allocations allowed). Zero-initialized at module load.
__device__ float  g_agg[NN * DD];    // h_in = x + sum(neighbors), fp32
__device__ __half g_xh[NN * DD];     // fp16 copy of x
__device__ __half g_y0h[NN * DD];    // fp16 layer-0 output
__device__ int    g_cnt[NN];
__device__ int    g_rowptr[NN + 1];
__device__ int    g_col[NE];
__device__ int    g_pos[NE];
__device__ int    g_part[NCHUNK];

// ---------------------------------------------------------------------------
// fp32 -> fp16 conversion of x (8 elements / thread)
// ---------------------------------------------------------------------------
__global__ void __launch_bounds__(256)
conv_kernel(const float* __restrict__ x) {
    int i = blockIdx.x * blockDim.x + threadIdx.x;
    if (i >= NN * DD / 8) return;
    float4 a = ((const float4*)x)[2 * i];
    float4 b = ((const float4*)x)[2 * i + 1];
    __half2 h[4];
    h[0] = __floats2half2_rn(a.x, a.y);
    h[1] = __floats2half2_rn(a.z, a.w);
    h[2] = __floats2half2_rn(b.x, b.y);
    h[3] = __floats2half2_rn(b.z, b.w);
    ((uint4*)g_xh)[i] = *(uint4*)h;
}

// ---------------------------------------------------------------------------
// CSR build: hist (atomic, records slot) -> scan1 -> scan2_add -> fill (no atomic)
// ---------------------------------------------------------------------------
__global__ void hist_kernel(const int* __restrict__ dst) {
    int e = blockIdx.x * blockDim.x + threadIdx.x;
    if (e < NE) g_pos[e] = atomicAdd(&g_cnt[dst[e]], 1);
}

// per-chunk inclusive scan (coalesced), chunk totals -> g_part; zeroes g_cnt
__global__ void __launch_bounds__(SCAN_T)
scan1_kernel() {
    __shared__ int s[SCAN_T];
    int t = threadIdx.x;
    int i = blockIdx.x * SCAN_T + t;
    int v = 0;
    if (i < NN) { v = g_cnt[i]; g_cnt[i] = 0; }
    s[t] = v;
    __syncthreads();
    #pragma unroll
    for (int off = 1; off < SCAN_T; off <<= 1) {
        int add = (t >= off) ? s[t - off] : 0;
        __syncthreads();
        s[t] += add;
        __syncthreads();
    }
    if (i < NN) g_rowptr[i + 1] = s[t];
    if (t == SCAN_T - 1) g_part[blockIdx.x] = s[t];
    if (i == 0) g_rowptr[0] = 0;
}

// add prefix of chunk totals; each block redundantly reduces <=48 ints (L2-hot)
__global__ void __launch_bounds__(SCAN_T)
scan2_add_kernel() {
    __shared__ int s_off;
    int b = blockIdx.x;
    if (b == 0) return;
    int t = threadIdx.x;
    if (t < 32) {
        int acc = 0;
        for (int j = t; j < b; j += 32) acc += g_part[j];
        #pragma unroll
        for (int o = 16; o > 0; o >>= 1)
            acc += __shfl_down_sync(0xffffffffu, acc, o);
        if (t == 0) s_off = acc;
    }
    __syncthreads();
    int off = s_off;
    int i = b * SCAN_T + t;
    if (i < NN) g_rowptr[i + 1] += off;
}

// atomic-free fill using precomputed slots
__global__ void fill_kernel(const int* __restrict__ src,
                            const int* __restrict__ dst) {
    int e = blockIdx.x * blockDim.x + threadIdx.x;
    if (e < NE) {
        int d = dst[e];
        g_col[g_rowptr[d] + g_pos[e]] = src[e];
    }
}

// ---------------------------------------------------------------------------
// fp16 gather: g_agg[n] = X[n] + sum_{j in N_in(n)} X[j]  (X fp16, acc fp32)
// 8 lanes per node, each lane owns 8 halfs (16B), 4-wide neighbor unroll.
// ---------------------------------------------------------------------------
__device__ __forceinline__ void acc_add(float* a, uint4 v) {
    const __half2* h = (const __half2*)&v;
    #pragma unroll
    for (int i = 0; i < 4; i++) {
        float2 f = __half22float2(h[i]);
        a[2 * i]     += f.x;
        a[2 * i + 1] += f.y;
    }
}

__global__ void __launch_bounds__(256)
gather_kernel(int in_scratch) {
    const __half* __restrict__ base = in_scratch ? g_y0h : g_xh;
    int t = blockIdx.x * blockDim.x + threadIdx.x;
    int node = t >> 3;
    if (node >= NN) return;
    int colh = (t & 7) << 3;   // half offset: 0,8,...,56

    float acc[8] = {0.f};
    acc_add(acc, *(const uint4*)(base + (size_t)node * DD + colh));

    int p   = g_rowptr[node];
    int end = g_rowptr[node + 1];

    for (; p + 3 < end; p += 4) {
        int j0 = g_col[p];
        int j1 = g_col[p + 1];
        int j2 = g_col[p + 2];
        int j3 = g_col[p + 3];
        uint4 a = *(const uint4*)(base + (size_t)j0 * DD + colh);
        uint4 b = *(const uint4*)(base + (size_t)j1 * DD + colh);
        uint4 c = *(const uint4*)(base + (size_t)j2 * DD + colh);
        uint4 d = *(const uint4*)(base + (size_t)j3 * DD + colh);
        acc_add(acc, a);
        acc_add(acc, b);
        acc_add(acc, c);
        acc_add(acc, d);
    }
    for (; p < end; p++) {
        uint4 a = *(const uint4*)(base + (size_t)g_col[p] * DD + colh);
        acc_add(acc, a);
    }

    float* o = g_agg + (size_t)node * DD + colh;
    *(float4*)o       = make_float4(acc[0], acc[1], acc[2], acc[3]);
    *(float4*)(o + 4) = make_float4(acc[4], acc[5], acc[6], acc[7]);
}

// ---------------------------------------------------------------------------
// fused MLP (scalar FFMA): out = tanh(g_agg @ W1 + b1) @ W2 + b2
// out_half=1 -> write fp16 to g_y0h; else fp32 to out.
// ---------------------------------------------------------------------------
__device__ __forceinline__ float fast_tanh(float x) {
    float y;
    asm("tanh.approx.f32 %0, %1;" : "=f"(y) : "f"(x));
    return y;
}

#define T_STRIDE 65
#define SMEM_FLOATS (4096 * 2 + 64 * T_STRIDE)   // 49408 B

__global__ void __launch_bounds__(128, 4)
mlp_kernel(const float* __restrict__ w1, const float* __restrict__ b1,
           const float* __restrict__ w2, const float* __restrict__ b2,
           float* __restrict__ out, int out_half) {
    extern __shared__ float sm[];
    float* sW1 = sm;                    // 64*64
    float* sW2 = sm + 4096;             // 64*64
    float* sT  = sm + 8192;             // 64 * T_STRIDE (reused for tanh(h))

    const int tid = threadIdx.x;
    const int n0 = blockIdx.x * 64;

    // ---- load weights into smem ----
    #pragma unroll
    for (int rep = 0; rep < 8; rep++) {
        int f4 = rep * 128 + tid;
        ((float4*)sW1)[f4] = ((const float4*)w1)[f4];
        ((float4*)sW2)[f4] = ((const float4*)w2)[f4];
    }

    // ---- load node tile into sT ----
    #pragma unroll
    for (int rep = 0; rep < 8; rep++) {
        int f4 = rep * 128 + tid;
        int n = f4 >> 4;
        int k = (f4 & 15) << 2;
        float4 v;
        if (n0 + n < NN) {
            v = *(const float4*)(g_agg + (size_t)(n0 + n) * DD + k);
        } else {
            v = make_float4(0.f, 0.f, 0.f, 0.f);
        }
        float* p = sT + n * T_STRIDE + k;
        p[0] = v.x; p[1] = v.y; p[2] = v.z; p[3] = v.w;
    }
    __syncthreads();

    const int ng = tid & 15;
    const int cg = tid >> 4;
    const int cb = cg * 8;

    float acc[4][8];

    // ---- GEMM1: h = T @ W1 + b1 ----
    {
        float bv[8];
        #pragma unroll
        for (int u = 0; u < 8; u++) bv[u] = b1[cb + u];
        #pragma unroll
        for (int j = 0; j < 4; j++)
            #pragma unroll
            for (int u = 0; u < 8; u++) acc[j][u] = bv[u];

        #pragma unroll 4
        for (int k = 0; k < 64; k++) {
            float4 wA = *(const float4*)(sW1 + k * 64 + cb);
            float4 wB = *(const float4*)(sW1 + k * 64 + cb + 4);
            float w[8] = {wA.x, wA.y, wA.z, wA.w, wB.x, wB.y, wB.z, wB.w};
            #pragma unroll
            for (int j = 0; j < 4; j++) {
                float tv = sT[(ng + 16 * j) * T_STRIDE + k];
                #pragma unroll
                for (int u = 0; u < 8; u++) acc[j][u] += tv * w[u];
            }
        }
    }

    // ---- tanh; overwrite sT ----
    __syncthreads();
    #pragma unroll
    for (int j = 0; j < 4; j++) {
        float* hrow = sT + (ng + 16 * j) * T_STRIDE + cb;
        #pragma unroll
        for (int u = 0; u < 8; u++)
            hrow[u] = fast_tanh(acc[j][u]);
    }
    __syncthreads();

    // ---- GEMM2: y = H @ W2 + b2 ----
    {
        float bv[8];
        #pragma unroll
        for (int u = 0; u < 8; u++) bv[u] = b2[cb + u];
        #pragma unroll
        for (int j = 0; j < 4; j++)
            #pragma unroll
            for (int u = 0; u < 8; u++) acc[j][u] = bv[u];

        #pragma unroll 4
        for (int k = 0; k < 64; k++) {
            float4 wA = *(const float4*)(sW2 + k * 64 + cb);
            float4 wB = *(const float4*)(sW2 + k * 64 + cb + 4);
            float w[8] = {wA.x, wA.y, wA.z, wA.w, wB.x, wB.y, wB.z, wB.w};
            #pragma unroll
            for (int j = 0; j < 4; j++) {
                float hv = sT[(ng + 16 * j) * T_STRIDE + k];
                #pragma unroll
                for (int u = 0; u < 8; u++) acc[j][u] += hv * w[u];
            }
        }
    }

    // ---- store ----
    #pragma unroll
    for (int j = 0; j < 4; j++) {
        int n = n0 + ng + 16 * j;
        if (n < NN) {
            if (out_half) {
                __half2 h[4];
                h[0] = __floats2half2_rn(acc[j][0], acc[j][1]);
                h[1] = __floats2half2_rn(acc[j][2], acc[j][3]);
                h[2] = __floats2half2_rn(acc[j][4], acc[j][5]);
                h[3] = __floats2half2_rn(acc[j][6], acc[j][7]);
                *(uint4*)(g_y0h + (size_t)n * DD + cb) = *(uint4*)h;
            } else {
                *(float4*)(out + (size_t)n * DD + cb) =
                    make_float4(acc[j][0], acc[j][1], acc[j][2], acc[j][3]);
                *(float4*)(out + (size_t)n * DD + cb + 4) =
                    make_float4(acc[j][4], acc[j][5], acc[j][6], acc[j][7]);
            }
        }
    }
}

// ---------------------------------------------------------------------------
// launch
// ---------------------------------------------------------------------------
extern "C" void kernel_launch(void* const* d_in, const int* in_sizes, int n_in,
                              void* d_out, int out_size) {
    const float* x    = (const float*)d_in[0];
    const int*   src  = (const int*)d_in[1];
    const int*   dst  = (const int*)d_in[2];
    const float* w1_0 = (const float*)d_in[3];
    const float* b1_0 = (const float*)d_in[4];
    const float* w2_0 = (const float*)d_in[5];
    const float* b2_0 = (const float*)d_in[6];
    const float* w1_1 = (const float*)d_in[7];
    const float* b1_1 = (const float*)d_in[8];
    const float* w2_1 = (const float*)d_in[9];
    const float* b2_1 = (const float*)d_in[10];
    float* out = (float*)d_out;

    const int smem_bytes = SMEM_FLOATS * sizeof(float);
    cudaFuncSetAttribute(mlp_kernel, cudaFuncAttributeMaxDynamicSharedMemorySize,
                         smem_bytes);

    const int convb = (NN * DD / 8 + 255) / 256;
    const int edgeb = (NE + 255) / 256;
    const int gathb = (NN * 8 + 255) / 256;
    const int mlpb  = (NN + 63) / 64;

    // ---- fp16 copy of x + CSR build ----
    conv_kernel<<<convb, 256>>>(x);
    hist_kernel<<<edgeb, 256>>>(dst);
    scan1_kernel<<<NCHUNK, SCAN_T>>>();
    scan2_add_kernel<<<NCHUNK, SCAN_T>>>();
    fill_kernel<<<edgeb, 256>>>(src, dst);

    // ---- layer 0 ----
    gather_kernel<<<gathb, 256>>>(/*in_scratch=*/0);
    mlp_kernel<<<mlpb, 128, smem_bytes>>>(w1_0, b1_0, w2_0, b2_0,
                                          out, /*out_half=*/1);

    // ---- layer 1 ----
    gather_kernel<<<gathb, 256>>>(/*in_scratch=*/1);
    mlp_kernel<<<mlpb, 128, smem_bytes>>>(w1_1, b1_1, w2_1, b2_1,
                                          out, /*out_half=*/0);
}